// round 13
// baseline (speedup 1.0000x reference)
#include <cuda_runtime.h>
#include <math.h>

// Problem constants
#define Bc   64
#define Tc   512
#define TPB  256
#define NCTA 128

// -------------------- scratch (static device globals; no allocation) --------------------
__device__ float g_xg[Bc * Tc * 2048];   // 256 MB: input-projection gates (reused per layer)
__device__ float g_seq[Bc * Tc * 256];   // 32 MB: y1 / y3 sequence buffer (reused)
__device__ float g_h[Bc * 512];          // recurrent h state (reused per layer)
__device__ float g_h0[Bc * 512];         // encoder2 final h
__device__ float g_g0[Bc * 1024];        // decoder1 constant pre-activation gates
__device__ unsigned g_bar_arrive;        // zero-init
__device__ unsigned g_bar_gen;           // zero-init

// -------------------- software grid barrier (128 co-resident CTAs) --------------------
__device__ __forceinline__ void grid_barrier(unsigned* s_phase) {
    __threadfence();           // make this CTA's global writes visible chip-wide
    __syncthreads();
    if (threadIdx.x == 0) {
        unsigned ph = *s_phase;
        unsigned a = atomicAdd(&g_bar_arrive, 1u);
        if (a == NCTA - 1u) {
            g_bar_arrive = 0u;
            __threadfence();
            atomicExch(&g_bar_gen, ph + 1u);
        } else {
            while (*(volatile unsigned*)&g_bar_gen == ph) { }
        }
        *s_phase = ph + 1u;
        __threadfence();       // acquire
    }
    __syncthreads();
}

// -------------------- tiled fp32 GEMM: Y[M,N] = X[M,K] @ W[N,K]^T + bias --------------------
// If lengths != nullptr, row tiles entirely past len[b] are skipped (their outputs are never read).
__global__ void __launch_bounds__(256) gemm_bias(
    const float* __restrict__ X, const float* __restrict__ W,
    const float* __restrict__ bias, float* __restrict__ Y,
    int M, int N, int K, const int* __restrict__ lengths)
{
    const int BM = 64, BN = 64, BK = 16;
    int n0 = blockIdx.x * BN;
    int m0 = blockIdx.y * BM;
    if (lengths) {
        int b  = m0 >> 9;        // m = b*512 + t
        int t0 = m0 & 511;
        if (t0 >= lengths[b]) return;
    }
    __shared__ float Xs[BK][BM + 4];
    __shared__ float Ws[BK][BN + 4];
    int tid = threadIdx.x;
    int tx = tid & 15, ty = tid >> 4;       // 16x16 threads, each 4x4 micro-tile
    int lm  = tid >> 2;                     // 0..63
    int lk4 = (tid & 3) * 4;                // 0,4,8,12

    float acc[4][4];
#pragma unroll
    for (int i = 0; i < 4; i++)
#pragma unroll
        for (int j = 0; j < 4; j++) acc[i][j] = 0.f;

    for (int k0 = 0; k0 < K; k0 += BK) {
        float4 xv = *(const float4*)&X[(size_t)(m0 + lm) * K + k0 + lk4];
        float4 wv = *(const float4*)&W[(size_t)(n0 + lm) * K + k0 + lk4];
        __syncthreads();
        Xs[lk4 + 0][lm] = xv.x; Xs[lk4 + 1][lm] = xv.y;
        Xs[lk4 + 2][lm] = xv.z; Xs[lk4 + 3][lm] = xv.w;
        Ws[lk4 + 0][lm] = wv.x; Ws[lk4 + 1][lm] = wv.y;
        Ws[lk4 + 2][lm] = wv.z; Ws[lk4 + 3][lm] = wv.w;
        __syncthreads();
#pragma unroll
        for (int k = 0; k < BK; k++) {
            float4 xr = *(const float4*)&Xs[k][ty * 4];
            float4 wr = *(const float4*)&Ws[k][tx * 4];
            float xa[4] = {xr.x, xr.y, xr.z, xr.w};
            float wa[4] = {wr.x, wr.y, wr.z, wr.w};
#pragma unroll
            for (int i = 0; i < 4; i++)
#pragma unroll
                for (int j = 0; j < 4; j++) acc[i][j] += xa[i] * wa[j];
        }
    }
    float bb[4];
#pragma unroll
    for (int j = 0; j < 4; j++) bb[j] = bias[n0 + tx * 4 + j];
#pragma unroll
    for (int i = 0; i < 4; i++) {
        size_t row = (size_t)(m0 + ty * 4 + i) * N + n0 + tx * 4;
#pragma unroll
        for (int j = 0; j < 4; j++) Y[row + j] = acc[i][j] + bb[j];
    }
}

// -------------------- persistent recurrent LSTM layer --------------------
// CTA cta owns units j0 = cta*U .. j0+U-1 (all 4 gates). c state lives in SMEM.
// Each step: stage full h [64,H] into SMEM, compute gate dots (S k-slices per task),
// pointwise LSTM update, write owned h slice to global, grid barrier.
template <int H, int U, int S, bool WRITE_Y, bool CONST_IN>
__global__ void __launch_bounds__(TPB, 1) lstm_rec(
    const float* __restrict__ xg,      // [B,T,4H] (or [B,4H] if CONST_IN)
    const float* __restrict__ whh,     // [4H,H]
    const int*   __restrict__ lengths, // [B]
    float*       __restrict__ hbuf,    // [B,H] global h state
    float*       __restrict__ yout)    // WRITE_Y: [B,T,H]; else final h -> [B,H]
{
    constexpr int Hp = H + 4;
    constexpr int R = 4 * U;
    constexpr int TASKS = Bc * U;
    static_assert(TASKS * S == TPB, "task/slice mismatch");

    extern __shared__ char smem_raw[];
    float* Ws   = (float*)smem_raw;          // R * Hp
    float* hs   = Ws + R * Hp;               // 64 * Hp
    float* cs   = hs + Bc * Hp;              // TASKS
    float* part = cs + TASKS;                // 4 * TPB
    int*   ls   = (int*)(part + 4 * TPB);    // 64
    __shared__ unsigned s_phase;

    const int tid = threadIdx.x;
    const int cta = blockIdx.x;
    const int j0 = cta * U;

    if (tid < Bc) ls[tid] = lengths[tid];
    // stage weight slice
    for (int idx = tid; idx < R * (H / 4); idx += TPB) {
        int r = idx / (H / 4), kk = idx % (H / 4);
        int g = r / U, u = r % U;
        float4 v = *(const float4*)&whh[(size_t)(g * H + j0 + u) * H + kk * 4];
        *(float4*)&Ws[r * Hp + kk * 4] = v;
    }
    for (int idx = tid; idx < TASKS; idx += TPB) cs[idx] = 0.f;
    for (int idx = tid; idx < Bc * U; idx += TPB) {
        int b = idx / U, u = idx % U;
        hbuf[b * H + j0 + u] = 0.f;
    }
    if (tid == 0) s_phase = *(volatile unsigned*)&g_bar_gen;
    grid_barrier(&s_phase);

    const int tt = tid % TASKS;
    const int sl = tid / TASKS;
    const int b  = tt / U;
    const int u  = tt % U;
    const float* w0 = &Ws[(0 * U + u) * Hp];
    const float* w1 = &Ws[(1 * U + u) * Hp];
    const float* w2 = &Ws[(2 * U + u) * Hp];
    const float* w3 = &Ws[(3 * U + u) * Hp];
    const float* hrow = &hs[b * Hp];
    constexpr int KS = H / S;
    const int kb = sl * KS;

    for (int t = 0; t < Tc; ++t) {
        // stage full h into smem
        for (int idx = tid; idx < Bc * (H / 4); idx += TPB) {
            int bb = idx / (H / 4), kk = idx % (H / 4);
            *(float4*)&hs[bb * Hp + kk * 4] = *(const float4*)&hbuf[bb * H + kk * 4];
        }
        __syncthreads();

        const bool valid = (t < ls[b]);
        float a0 = 0.f, a1 = 0.f, a2 = 0.f, a3 = 0.f;
        if (valid) {
#pragma unroll 4
            for (int k = kb; k < kb + KS; k += 4) {
                float4 hv = *(const float4*)&hrow[k];
                float4 v0 = *(const float4*)&w0[k];
                float4 v1 = *(const float4*)&w1[k];
                float4 v2 = *(const float4*)&w2[k];
                float4 v3 = *(const float4*)&w3[k];
                a0 += hv.x * v0.x + hv.y * v0.y + hv.z * v0.z + hv.w * v0.w;
                a1 += hv.x * v1.x + hv.y * v1.y + hv.z * v1.z + hv.w * v1.w;
                a2 += hv.x * v2.x + hv.y * v2.y + hv.z * v2.z + hv.w * v2.w;
                a3 += hv.x * v3.x + hv.y * v3.y + hv.z * v3.z + hv.w * v3.w;
            }
        }
        if (S > 1) {
            part[tid * 4 + 0] = a0; part[tid * 4 + 1] = a1;
            part[tid * 4 + 2] = a2; part[tid * 4 + 3] = a3;
            __syncthreads();
            if (tid < TASKS && valid) {
#pragma unroll
                for (int s2 = 1; s2 < S; ++s2) {
                    int o = (s2 * TASKS + tid) * 4;
                    a0 += part[o + 0]; a1 += part[o + 1];
                    a2 += part[o + 2]; a3 += part[o + 3];
                }
            }
        }
        if ((S == 1 || tid < TASKS) && valid) {
            const float* xr = CONST_IN ? &xg[(size_t)b * 4 * H]
                                       : &xg[((size_t)b * Tc + t) * 4 * H];
            const int j = j0 + u;
            float gi = a0 + xr[0 * H + j];
            float gf = a1 + xr[1 * H + j];
            float gg = a2 + xr[2 * H + j];
            float go = a3 + xr[3 * H + j];
            float ig = 1.f / (1.f + expf(-gi));
            float fg = 1.f / (1.f + expf(-gf));
            float gv = tanhf(gg);
            float og = 1.f / (1.f + expf(-go));
            float c  = fg * cs[tt] + ig * gv;
            cs[tt] = c;
            float hn = og * tanhf(c);
            hbuf[b * H + j] = hn;
            if (WRITE_Y) yout[((size_t)b * Tc + t) * H + j] = hn;
        }
        grid_barrier(&s_phase);
    }

    if (!WRITE_Y) {  // export final (frozen) h slice
        for (int idx = tid; idx < Bc * U; idx += TPB) {
            int bb = idx / U, uu = idx % U;
            yout[bb * H + j0 + uu] = hbuf[bb * H + j0 + uu];
        }
    }
}

// -------------------- classifier head --------------------
__global__ void __launch_bounds__(256) head_kernel(
    const float* __restrict__ h0,  // [64,512]
    const float* __restrict__ lw1, const float* __restrict__ lb1,  // [256,512],[256]
    const float* __restrict__ lw2, const float* __restrict__ lb2,  // [2,256],[2]
    float* __restrict__ outp)      // [64,2]
{
    __shared__ float hv[512];
    __shared__ float hid[256];
    __shared__ float lg[2];
    int bidx = blockIdx.x, tid = threadIdx.x;
    hv[tid]       = h0[bidx * 512 + tid];
    hv[tid + 256] = h0[bidx * 512 + 256 + tid];
    __syncthreads();
    float acc = lb1[tid];
    const float* wr = &lw1[tid * 512];
#pragma unroll 4
    for (int k = 0; k < 512; k += 4) {
        float4 w = *(const float4*)&wr[k];
        acc += w.x * hv[k] + w.y * hv[k + 1] + w.z * hv[k + 2] + w.w * hv[k + 3];
    }
    hid[tid] = fmaxf(acc, 0.f);
    __syncthreads();
    if (tid < 64) {
        int c = tid >> 5, lane = tid & 31;
        float p = 0.f;
        for (int k = lane; k < 256; k += 32) p += hid[k] * lw2[c * 256 + k];
#pragma unroll
        for (int off = 16; off; off >>= 1) p += __shfl_down_sync(0xffffffffu, p, off);
        if (lane == 0) lg[c] = p + lb2[c];
    }
    __syncthreads();
    if (tid == 0) {
        float m = fmaxf(lg[0], lg[1]);
        float lse = m + logf(expf(lg[0] - m) + expf(lg[1] - m));
        outp[bidx * 2 + 0] = lg[0] - lse;
        outp[bidx * 2 + 1] = lg[1] - lse;
    }
}

// -------------------- launcher --------------------
static inline int lstm_smem_bytes(int H, int U) {
    int Hp = H + 4, R = 4 * U, TASKS = Bc * U;
    return 4 * (R * Hp + Bc * Hp + TASKS + 4 * TPB) + Bc * 4 + 16;
}

extern "C" void kernel_launch(void* const* d_in, const int* in_sizes, int n_in,
                              void* d_out, int out_size) {
    const float* x       = (const float*)d_in[0];
    const int*   lengths = (const int*)  d_in[1];
    const float* e1_wih  = (const float*)d_in[2];
    const float* e1_whh  = (const float*)d_in[3];
    const float* e1_b    = (const float*)d_in[4];
    const float* e2_wih  = (const float*)d_in[5];
    const float* e2_whh  = (const float*)d_in[6];
    const float* e2_b    = (const float*)d_in[7];
    const float* d1_wih  = (const float*)d_in[8];
    const float* d1_whh  = (const float*)d_in[9];
    const float* d1_b    = (const float*)d_in[10];
    const float* d2_wih  = (const float*)d_in[11];
    const float* d2_whh  = (const float*)d_in[12];
    const float* d2_b    = (const float*)d_in[13];
    const float* lw1     = (const float*)d_in[14];
    const float* lb1     = (const float*)d_in[15];
    const float* lw2     = (const float*)d_in[16];
    const float* lb2     = (const float*)d_in[17];
    float* out = (float*)d_out;

    float *xgp, *seqp, *hp, *h0p, *g0p;
    cudaGetSymbolAddress((void**)&xgp,  g_xg);
    cudaGetSymbolAddress((void**)&seqp, g_seq);
    cudaGetSymbolAddress((void**)&hp,   g_h);
    cudaGetSymbolAddress((void**)&h0p,  g_h0);
    cudaGetSymbolAddress((void**)&g0p,  g_g0);

    const int SMEM_E1 = lstm_smem_bytes(256, 2);
    const int SMEM_E2 = lstm_smem_bytes(512, 4);
    const int SMEM_D2 = lstm_smem_bytes(128, 1);
    cudaFuncSetAttribute((const void*)lstm_rec<256, 2, 2, true,  false>,
                         cudaFuncAttributeMaxDynamicSharedMemorySize, SMEM_E1);
    cudaFuncSetAttribute((const void*)lstm_rec<512, 4, 1, false, false>,
                         cudaFuncAttributeMaxDynamicSharedMemorySize, SMEM_E2);
    cudaFuncSetAttribute((const void*)lstm_rec<256, 2, 2, true,  true>,
                         cudaFuncAttributeMaxDynamicSharedMemorySize, SMEM_E1);
    cudaFuncSetAttribute((const void*)lstm_rec<128, 1, 4, true,  false>,
                         cudaFuncAttributeMaxDynamicSharedMemorySize, SMEM_D2);

    const int M = Bc * Tc;  // 32768

    // zero output (valid entries overwritten; invalid stay 0 per masked semantics)
    cudaMemsetAsync(d_out, 0, (size_t)out_size * sizeof(float));

    // encoder 1: proj + recurrence -> g_seq [B,T,256]
    gemm_bias<<<dim3(1024 / 64, M / 64), 256>>>(x, e1_wih, e1_b, xgp, M, 1024, 128, lengths);
    lstm_rec<256, 2, 2, true, false><<<NCTA, TPB, SMEM_E1>>>(xgp, e1_whh, lengths, hp, seqp);

    // encoder 2: proj + recurrence -> h0 [B,512]
    gemm_bias<<<dim3(2048 / 64, M / 64), 256>>>(seqp, e2_wih, e2_b, xgp, M, 2048, 256, lengths);
    lstm_rec<512, 4, 1, false, false><<<NCTA, TPB, SMEM_E2>>>(xgp, e2_whh, lengths, hp, h0p);

    // decoder 1: constant input per batch -> g0 = h0 @ d1_wih^T + d1_b
    gemm_bias<<<dim3(1024 / 64, 1), 256>>>(h0p, d1_wih, d1_b, g0p, Bc, 1024, 512, nullptr);
    lstm_rec<256, 2, 2, true, true><<<NCTA, TPB, SMEM_E1>>>(g0p, d1_whh, lengths, hp, seqp);

    // decoder 2: proj + recurrence -> out [B,T,128] (written directly to d_out)
    gemm_bias<<<dim3(512 / 64, M / 64), 256>>>(seqp, d2_wih, d2_b, xgp, M, 512, 256, lengths);
    lstm_rec<128, 1, 4, true, false><<<NCTA, TPB, SMEM_D2>>>(xgp, d2_whh, lengths, hp, out);

    // classifier head -> label [B,2] at end of d_out
    head_kernel<<<Bc, 256>>>(h0p, lw1, lb1, lw2, lb2, out + (size_t)out_size - 2 * Bc);
}

// round 14
// speedup vs baseline: 1.0020x; 1.0020x over previous
#include <cuda_runtime.h>
#include <math.h>

// Problem constants
#define Bc   64
#define Tc   512
#define TPB  256
#define NCTA 128

// -------------------- scratch (static device globals; no allocation) --------------------
__device__ float g_xg[Bc * Tc * 2048];   // 256 MB: input-projection gates (reused per layer)
__device__ float g_seq[Bc * Tc * 256];   // 32 MB: y1 / y3 sequence buffer (reused)
__device__ float g_h[Bc * 512];          // recurrent h state (reused per layer)
__device__ float g_h0[Bc * 512];         // encoder2 final h
__device__ float g_g0[Bc * 1024];        // decoder1 constant pre-activation gates
__device__ unsigned g_bar_arrive;        // zero-init
__device__ unsigned g_bar_gen;           // zero-init

// -------------------- software grid barrier (128 co-resident CTAs) --------------------
__device__ __forceinline__ void grid_barrier(unsigned* s_phase) {
    __threadfence();           // make this CTA's global writes visible chip-wide
    __syncthreads();
    if (threadIdx.x == 0) {
        unsigned ph = *s_phase;
        unsigned a = atomicAdd(&g_bar_arrive, 1u);
        if (a == NCTA - 1u) {
            g_bar_arrive = 0u;
            __threadfence();
            atomicExch(&g_bar_gen, ph + 1u);
        } else {
            while (*(volatile unsigned*)&g_bar_gen == ph) { }
        }
        *s_phase = ph + 1u;
        __threadfence();       // acquire
    }
    __syncthreads();
}

// -------------------- tiled fp32 GEMM: Y[M,N] = X[M,K] @ W[N,K]^T + bias --------------------
// If lengths != nullptr, row tiles entirely past len[b] are skipped (their outputs are never read).
__global__ void __launch_bounds__(256) gemm_bias(
    const float* __restrict__ X, const float* __restrict__ W,
    const float* __restrict__ bias, float* __restrict__ Y,
    int M, int N, int K, const int* __restrict__ lengths)
{
    const int BM = 64, BN = 64, BK = 16;
    int n0 = blockIdx.x * BN;
    int m0 = blockIdx.y * BM;
    if (lengths) {
        int b  = m0 >> 9;        // m = b*512 + t
        int t0 = m0 & 511;
        if (t0 >= lengths[b]) return;
    }
    __shared__ float Xs[BK][BM + 4];
    __shared__ float Ws[BK][BN + 4];
    int tid = threadIdx.x;
    int tx = tid & 15, ty = tid >> 4;       // 16x16 threads, each 4x4 micro-tile
    int lm  = tid >> 2;                     // 0..63
    int lk4 = (tid & 3) * 4;                // 0,4,8,12

    float acc[4][4];
#pragma unroll
    for (int i = 0; i < 4; i++)
#pragma unroll
        for (int j = 0; j < 4; j++) acc[i][j] = 0.f;

    for (int k0 = 0; k0 < K; k0 += BK) {
        float4 xv = *(const float4*)&X[(size_t)(m0 + lm) * K + k0 + lk4];
        float4 wv = *(const float4*)&W[(size_t)(n0 + lm) * K + k0 + lk4];
        __syncthreads();
        Xs[lk4 + 0][lm] = xv.x; Xs[lk4 + 1][lm] = xv.y;
        Xs[lk4 + 2][lm] = xv.z; Xs[lk4 + 3][lm] = xv.w;
        Ws[lk4 + 0][lm] = wv.x; Ws[lk4 + 1][lm] = wv.y;
        Ws[lk4 + 2][lm] = wv.z; Ws[lk4 + 3][lm] = wv.w;
        __syncthreads();
#pragma unroll
        for (int k = 0; k < BK; k++) {
            float4 xr = *(const float4*)&Xs[k][ty * 4];
            float4 wr = *(const float4*)&Ws[k][tx * 4];
            float xa[4] = {xr.x, xr.y, xr.z, xr.w};
            float wa[4] = {wr.x, wr.y, wr.z, wr.w};
#pragma unroll
            for (int i = 0; i < 4; i++)
#pragma unroll
                for (int j = 0; j < 4; j++) acc[i][j] += xa[i] * wa[j];
        }
    }
    float bb[4];
#pragma unroll
    for (int j = 0; j < 4; j++) bb[j] = bias[n0 + tx * 4 + j];
#pragma unroll
    for (int i = 0; i < 4; i++) {
        size_t row = (size_t)(m0 + ty * 4 + i) * N + n0 + tx * 4;
#pragma unroll
        for (int j = 0; j < 4; j++) Y[row + j] = acc[i][j] + bb[j];
    }
}

// -------------------- persistent recurrent LSTM layer --------------------
// CTA cta owns units j0 = cta*U .. j0+U-1 (all 4 gates). c state lives in SMEM.
// Each step: stage full h [64,H] into SMEM, compute gate dots (S k-slices per task),
// pointwise LSTM update, write owned h slice to global, grid barrier.
template <int H, int U, int S, bool WRITE_Y, bool CONST_IN>
__global__ void __launch_bounds__(TPB, 1) lstm_rec(
    const float* __restrict__ xg,      // [B,T,4H] (or [B,4H] if CONST_IN)
    const float* __restrict__ whh,     // [4H,H]
    const int*   __restrict__ lengths, // [B]
    float*       __restrict__ hbuf,    // [B,H] global h state
    float*       __restrict__ yout)    // WRITE_Y: [B,T,H]; else final h -> [B,H]
{
    constexpr int Hp = H + 4;
    constexpr int R = 4 * U;
    constexpr int TASKS = Bc * U;
    static_assert(TASKS * S == TPB, "task/slice mismatch");

    extern __shared__ char smem_raw[];
    float* Ws   = (float*)smem_raw;          // R * Hp
    float* hs   = Ws + R * Hp;               // 64 * Hp
    float* cs   = hs + Bc * Hp;              // TASKS
    float* part = cs + TASKS;                // 4 * TPB
    int*   ls   = (int*)(part + 4 * TPB);    // 64
    __shared__ unsigned s_phase;

    const int tid = threadIdx.x;
    const int cta = blockIdx.x;
    const int j0 = cta * U;

    if (tid < Bc) ls[tid] = lengths[tid];
    // stage weight slice
    for (int idx = tid; idx < R * (H / 4); idx += TPB) {
        int r = idx / (H / 4), kk = idx % (H / 4);
        int g = r / U, u = r % U;
        float4 v = *(const float4*)&whh[(size_t)(g * H + j0 + u) * H + kk * 4];
        *(float4*)&Ws[r * Hp + kk * 4] = v;
    }
    for (int idx = tid; idx < TASKS; idx += TPB) cs[idx] = 0.f;
    for (int idx = tid; idx < Bc * U; idx += TPB) {
        int b = idx / U, u = idx % U;
        hbuf[b * H + j0 + u] = 0.f;
    }
    if (tid == 0) s_phase = *(volatile unsigned*)&g_bar_gen;
    grid_barrier(&s_phase);

    const int tt = tid % TASKS;
    const int sl = tid / TASKS;
    const int b  = tt / U;
    const int u  = tt % U;
    const float* w0 = &Ws[(0 * U + u) * Hp];
    const float* w1 = &Ws[(1 * U + u) * Hp];
    const float* w2 = &Ws[(2 * U + u) * Hp];
    const float* w3 = &Ws[(3 * U + u) * Hp];
    const float* hrow = &hs[b * Hp];
    constexpr int KS = H / S;
    const int kb = sl * KS;

    for (int t = 0; t < Tc; ++t) {
        // stage full h into smem
        for (int idx = tid; idx < Bc * (H / 4); idx += TPB) {
            int bb = idx / (H / 4), kk = idx % (H / 4);
            *(float4*)&hs[bb * Hp + kk * 4] = *(const float4*)&hbuf[bb * H + kk * 4];
        }
        __syncthreads();

        const bool valid = (t < ls[b]);
        float a0 = 0.f, a1 = 0.f, a2 = 0.f, a3 = 0.f;
        if (valid) {
#pragma unroll 4
            for (int k = kb; k < kb + KS; k += 4) {
                float4 hv = *(const float4*)&hrow[k];
                float4 v0 = *(const float4*)&w0[k];
                float4 v1 = *(const float4*)&w1[k];
                float4 v2 = *(const float4*)&w2[k];
                float4 v3 = *(const float4*)&w3[k];
                a0 += hv.x * v0.x + hv.y * v0.y + hv.z * v0.z + hv.w * v0.w;
                a1 += hv.x * v1.x + hv.y * v1.y + hv.z * v1.z + hv.w * v1.w;
                a2 += hv.x * v2.x + hv.y * v2.y + hv.z * v2.z + hv.w * v2.w;
                a3 += hv.x * v3.x + hv.y * v3.y + hv.z * v3.z + hv.w * v3.w;
            }
        }
        if (S > 1) {
            part[tid * 4 + 0] = a0; part[tid * 4 + 1] = a1;
            part[tid * 4 + 2] = a2; part[tid * 4 + 3] = a3;
            __syncthreads();
            if (tid < TASKS && valid) {
#pragma unroll
                for (int s2 = 1; s2 < S; ++s2) {
                    int o = (s2 * TASKS + tid) * 4;
                    a0 += part[o + 0]; a1 += part[o + 1];
                    a2 += part[o + 2]; a3 += part[o + 3];
                }
            }
        }
        if ((S == 1 || tid < TASKS) && valid) {
            const float* xr = CONST_IN ? &xg[(size_t)b * 4 * H]
                                       : &xg[((size_t)b * Tc + t) * 4 * H];
            const int j = j0 + u;
            float gi = a0 + xr[0 * H + j];
            float gf = a1 + xr[1 * H + j];
            float gg = a2 + xr[2 * H + j];
            float go = a3 + xr[3 * H + j];
            float ig = 1.f / (1.f + expf(-gi));
            float fg = 1.f / (1.f + expf(-gf));
            float gv = tanhf(gg);
            float og = 1.f / (1.f + expf(-go));
            float c  = fg * cs[tt] + ig * gv;
            cs[tt] = c;
            float hn = og * tanhf(c);
            hbuf[b * H + j] = hn;
            if (WRITE_Y) yout[((size_t)b * Tc + t) * H + j] = hn;
        }
        grid_barrier(&s_phase);
    }

    if (!WRITE_Y) {  // export final (frozen) h slice
        for (int idx = tid; idx < Bc * U; idx += TPB) {
            int bb = idx / U, uu = idx % U;
            yout[bb * H + j0 + uu] = hbuf[bb * H + j0 + uu];
        }
    }
}

// -------------------- classifier head --------------------
__global__ void __launch_bounds__(256) head_kernel(
    const float* __restrict__ h0,  // [64,512]
    const float* __restrict__ lw1, const float* __restrict__ lb1,  // [256,512],[256]
    const float* __restrict__ lw2, const float* __restrict__ lb2,  // [2,256],[2]
    float* __restrict__ outp)      // [64,2]
{
    __shared__ float hv[512];
    __shared__ float hid[256];
    __shared__ float lg[2];
    int bidx = blockIdx.x, tid = threadIdx.x;
    hv[tid]       = h0[bidx * 512 + tid];
    hv[tid + 256] = h0[bidx * 512 + 256 + tid];
    __syncthreads();
    float acc = lb1[tid];
    const float* wr = &lw1[tid * 512];
#pragma unroll 4
    for (int k = 0; k < 512; k += 4) {
        float4 w = *(const float4*)&wr[k];
        acc += w.x * hv[k] + w.y * hv[k + 1] + w.z * hv[k + 2] + w.w * hv[k + 3];
    }
    hid[tid] = fmaxf(acc, 0.f);
    __syncthreads();
    if (tid < 64) {
        int c = tid >> 5, lane = tid & 31;
        float p = 0.f;
        for (int k = lane; k < 256; k += 32) p += hid[k] * lw2[c * 256 + k];
#pragma unroll
        for (int off = 16; off; off >>= 1) p += __shfl_down_sync(0xffffffffu, p, off);
        if (lane == 0) lg[c] = p + lb2[c];
    }
    __syncthreads();
    if (tid == 0) {
        float m = fmaxf(lg[0], lg[1]);
        float lse = m + logf(expf(lg[0] - m) + expf(lg[1] - m));
        outp[bidx * 2 + 0] = lg[0] - lse;
        outp[bidx * 2 + 1] = lg[1] - lse;
    }
}

// -------------------- launcher --------------------
static inline int lstm_smem_bytes(int H, int U) {
    int Hp = H + 4, R = 4 * U, TASKS = Bc * U;
    return 4 * (R * Hp + Bc * Hp + TASKS + 4 * TPB) + Bc * 4 + 16;
}

extern "C" void kernel_launch(void* const* d_in, const int* in_sizes, int n_in,
                              void* d_out, int out_size) {
    const float* x       = (const float*)d_in[0];
    const int*   lengths = (const int*)  d_in[1];
    const float* e1_wih  = (const float*)d_in[2];
    const float* e1_whh  = (const float*)d_in[3];
    const float* e1_b    = (const float*)d_in[4];
    const float* e2_wih  = (const float*)d_in[5];
    const float* e2_whh  = (const float*)d_in[6];
    const float* e2_b    = (const float*)d_in[7];
    const float* d1_wih  = (const float*)d_in[8];
    const float* d1_whh  = (const float*)d_in[9];
    const float* d1_b    = (const float*)d_in[10];
    const float* d2_wih  = (const float*)d_in[11];
    const float* d2_whh  = (const float*)d_in[12];
    const float* d2_b    = (const float*)d_in[13];
    const float* lw1     = (const float*)d_in[14];
    const float* lb1     = (const float*)d_in[15];
    const float* lw2     = (const float*)d_in[16];
    const float* lb2     = (const float*)d_in[17];
    float* out = (float*)d_out;

    float *xgp, *seqp, *hp, *h0p, *g0p;
    cudaGetSymbolAddress((void**)&xgp,  g_xg);
    cudaGetSymbolAddress((void**)&seqp, g_seq);
    cudaGetSymbolAddress((void**)&hp,   g_h);
    cudaGetSymbolAddress((void**)&h0p,  g_h0);
    cudaGetSymbolAddress((void**)&g0p,  g_g0);

    const int SMEM_E1 = lstm_smem_bytes(256, 2);
    const int SMEM_E2 = lstm_smem_bytes(512, 4);
    const int SMEM_D2 = lstm_smem_bytes(128, 1);
    cudaFuncSetAttribute((const void*)lstm_rec<256, 2, 2, true,  false>,
                         cudaFuncAttributeMaxDynamicSharedMemorySize, SMEM_E1);
    cudaFuncSetAttribute((const void*)lstm_rec<512, 4, 1, false, false>,
                         cudaFuncAttributeMaxDynamicSharedMemorySize, SMEM_E2);
    cudaFuncSetAttribute((const void*)lstm_rec<256, 2, 2, true,  true>,
                         cudaFuncAttributeMaxDynamicSharedMemorySize, SMEM_E1);
    cudaFuncSetAttribute((const void*)lstm_rec<128, 1, 4, true,  false>,
                         cudaFuncAttributeMaxDynamicSharedMemorySize, SMEM_D2);

    const int M = Bc * Tc;  // 32768

    // zero output (valid entries overwritten; invalid stay 0 per masked semantics)
    cudaMemsetAsync(d_out, 0, (size_t)out_size * sizeof(float));

    // encoder 1: proj + recurrence -> g_seq [B,T,256]
    gemm_bias<<<dim3(1024 / 64, M / 64), 256>>>(x, e1_wih, e1_b, xgp, M, 1024, 128, lengths);
    lstm_rec<256, 2, 2, true, false><<<NCTA, TPB, SMEM_E1>>>(xgp, e1_whh, lengths, hp, seqp);

    // encoder 2: proj + recurrence -> h0 [B,512]
    gemm_bias<<<dim3(2048 / 64, M / 64), 256>>>(seqp, e2_wih, e2_b, xgp, M, 2048, 256, lengths);
    lstm_rec<512, 4, 1, false, false><<<NCTA, TPB, SMEM_E2>>>(xgp, e2_whh, lengths, hp, h0p);

    // decoder 1: constant input per batch -> g0 = h0 @ d1_wih^T + d1_b
    gemm_bias<<<dim3(1024 / 64, 1), 256>>>(h0p, d1_wih, d1_b, g0p, Bc, 1024, 512, nullptr);
    lstm_rec<256, 2, 2, true, true><<<NCTA, TPB, SMEM_E1>>>(g0p, d1_whh, lengths, hp, seqp);

    // decoder 2: proj + recurrence -> out [B,T,128] (written directly to d_out)
    gemm_bias<<<dim3(512 / 64, M / 64), 256>>>(seqp, d2_wih, d2_b, xgp, M, 512, 256, lengths);
    lstm_rec<128, 1, 4, true, false><<<NCTA, TPB, SMEM_D2>>>(xgp, d2_whh, lengths, hp, out);

    // classifier head -> label [B,2] at end of d_out
    head_kernel<<<Bc, 256>>>(h0p, lw1, lb1, lw2, lb2, out + (size_t)out_size - 2 * Bc);
}

// round 15
// speedup vs baseline: 1.0608x; 1.0587x over previous
#include <cuda_runtime.h>
#include <math.h>

#define Bc   64
#define Tc   512
#define TPB  512
#define NCTA 128

// -------------------- scratch (static device globals; no allocation) --------------------
__device__ float g_xg[Bc * Tc * 2048];   // input-projection gates (reused per layer)
__device__ float g_seq[Bc * Tc * 256];   // y1 / y3 sequence buffer (reused)
__device__ float g_h[Bc * 512];          // recurrent h state (reused per layer)
__device__ float g_h0[Bc * 512];         // encoder2 final h
__device__ float g_g0[Bc * 1024];        // decoder1 constant pre-activation gates
__device__ unsigned g_grp[16 * 32];      // group arrival counters (128B apart), monotonic
__device__ unsigned g_root;              // root arrival counter, monotonic
__device__ unsigned g_bar_gen;           // generation, monotonic

// -------------------- packed f32x2 fma --------------------
__device__ __forceinline__ void ffma2(unsigned long long& a,
                                      unsigned long long x, unsigned long long y) {
    asm("fma.rn.f32x2 %0, %1, %2, %0;" : "+l"(a) : "l"(x), "l"(y));
}
__device__ __forceinline__ float f2sum(unsigned long long a) {
    return __uint_as_float((unsigned)a) + __uint_as_float((unsigned)(a >> 32));
}

// -------------------- hierarchical grid barrier (128 CTAs: 16 groups x 8) ------------
__device__ __forceinline__ void grid_barrier(unsigned* s_phase) {
    __threadfence();
    __syncthreads();
    if (threadIdx.x == 0) {
        unsigned ph = *s_phase;
        unsigned g = blockIdx.x >> 3;
        unsigned a = atomicAdd(&g_grp[g << 5], 1u) + 1u;
        if ((a & 7u) == 0u) {                    // 8th arrival in group this phase
            unsigned r = atomicAdd(&g_root, 1u) + 1u;
            if ((r & 15u) == 0u) {               // 16th group -> release
                __threadfence();
                atomicAdd(&g_bar_gen, 1u);
            }
        }
        while (*(volatile unsigned*)&g_bar_gen == ph) { }
        *s_phase = ph + 1u;
        __threadfence();
    }
    __syncthreads();
}

// -------------------- tiled fp32 GEMM: Y[M,N] = X[M,K] @ W[N,K]^T + bias ----------------
__global__ void __launch_bounds__(256) gemm_bias(
    const float* __restrict__ X, const float* __restrict__ W,
    const float* __restrict__ bias, float* __restrict__ Y,
    int M, int N, int K, const int* __restrict__ lengths)
{
    const int BM = 64, BN = 64, BK = 16;
    int n0 = blockIdx.x * BN;
    int m0 = blockIdx.y * BM;
    if (lengths) {
        int b = m0 >> 9, t0 = m0 & 511;
        if (t0 >= lengths[b]) return;            // rows past length never read downstream
    }
    __shared__ float Xs[BK][BM + 4];
    __shared__ float Ws[BK][BN + 4];
    int tid = threadIdx.x;
    int tx = tid & 15, ty = tid >> 4;
    int lm = tid >> 2, lk4 = (tid & 3) * 4;

    float acc[4][4];
#pragma unroll
    for (int i = 0; i < 4; i++)
#pragma unroll
        for (int j = 0; j < 4; j++) acc[i][j] = 0.f;

    for (int k0 = 0; k0 < K; k0 += BK) {
        float4 xv = *(const float4*)&X[(size_t)(m0 + lm) * K + k0 + lk4];
        float4 wv = *(const float4*)&W[(size_t)(n0 + lm) * K + k0 + lk4];
        __syncthreads();
        Xs[lk4 + 0][lm] = xv.x; Xs[lk4 + 1][lm] = xv.y;
        Xs[lk4 + 2][lm] = xv.z; Xs[lk4 + 3][lm] = xv.w;
        Ws[lk4 + 0][lm] = wv.x; Ws[lk4 + 1][lm] = wv.y;
        Ws[lk4 + 2][lm] = wv.z; Ws[lk4 + 3][lm] = wv.w;
        __syncthreads();
#pragma unroll
        for (int k = 0; k < BK; k++) {
            float4 xr = *(const float4*)&Xs[k][ty * 4];
            float4 wr = *(const float4*)&Ws[k][tx * 4];
            float xa[4] = {xr.x, xr.y, xr.z, xr.w};
            float wa[4] = {wr.x, wr.y, wr.z, wr.w};
#pragma unroll
            for (int i = 0; i < 4; i++)
#pragma unroll
                for (int j = 0; j < 4; j++) acc[i][j] += xa[i] * wa[j];
        }
    }
    float bb[4];
#pragma unroll
    for (int j = 0; j < 4; j++) bb[j] = bias[n0 + tx * 4 + j];
#pragma unroll
    for (int i = 0; i < 4; i++) {
        size_t row = (size_t)(m0 + ty * 4 + i) * N + n0 + tx * 4;
#pragma unroll
        for (int j = 0; j < 4; j++) Y[row + j] = acc[i][j] + bb[j];
    }
}

// -------------------- persistent recurrent LSTM layer --------------------
// CTA owns U hidden units (4U gate rows, weights in smem). Per step: prefetch xg,
// broadcast h into smem, k-sliced packed-f32x2 gate dots, smem reduce, pointwise, barrier.
template <int H, int U, int S, bool WRITE_Y, bool CONST_IN>
__global__ void __launch_bounds__(TPB, 1) lstm_rec(
    const float* __restrict__ xg,      // [B,T,4H] (or [B,4H] if CONST_IN)
    const float* __restrict__ whh,     // [4H,H]
    const int*   __restrict__ lengths, // [B]
    float*       __restrict__ hbuf,    // [B,H] global h state
    float*       __restrict__ yout)    // WRITE_Y: [B,T,H]; else final h -> [B,H]
{
    constexpr int Hp = H + 4;
    constexpr int R = 4 * U;
    constexpr int TASKS = Bc * U;
    static_assert(TASKS * S == TPB, "task/slice mismatch");

    extern __shared__ char smem_raw[];
    float* Ws   = (float*)smem_raw;          // R * Hp
    float* hs   = Ws + R * Hp;               // 64 * Hp
    float* cs   = hs + Bc * Hp;              // TASKS
    float* part = cs + TASKS;                // 4 * TPB
    int*   ls   = (int*)(part + 4 * TPB);    // 64
    __shared__ unsigned s_phase;

    const int tid = threadIdx.x;
    const int j0 = blockIdx.x * U;

    if (tid < Bc) ls[tid] = lengths[tid];
    for (int idx = tid; idx < R * (H / 4); idx += TPB) {
        int r = idx / (H / 4), kk = idx % (H / 4);
        int g = r / U, u = r % U;
        float4 v = *(const float4*)&whh[(size_t)(g * H + j0 + u) * H + kk * 4];
        *(float4*)&Ws[r * Hp + kk * 4] = v;
    }
    for (int idx = tid; idx < TASKS; idx += TPB) cs[idx] = 0.f;
    for (int idx = tid; idx < Bc * U; idx += TPB)
        hbuf[(idx / U) * H + j0 + (idx % U)] = 0.f;
    if (tid == 0) s_phase = *(volatile unsigned*)&g_bar_gen;
    grid_barrier(&s_phase);

    const int tt = tid % TASKS;
    const int sl = tid / TASKS;
    const int b  = tt / U;
    const int u  = tt % U;
    const int j  = j0 + u;
    const float* w0 = &Ws[(0 * U + u) * Hp];
    const float* w1 = &Ws[(1 * U + u) * Hp];
    const float* w2 = &Ws[(2 * U + u) * Hp];
    const float* w3 = &Ws[(3 * U + u) * Hp];
    const float* hrow = &hs[b * Hp];
    constexpr int KS = H / S;
    const int kb = sl * KS;

    for (int t = 0; t < Tc; ++t) {
        const bool valid = (t < ls[b]);
        // prefetch xg (DRAM) before h staging to overlap latency
        float x0 = 0.f, x1 = 0.f, x2 = 0.f, x3 = 0.f;
        if (sl == 0 && valid) {
            const float* xr = CONST_IN ? &xg[(size_t)b * 4 * H]
                                       : &xg[((size_t)b * Tc + t) * 4 * H];
            x0 = xr[0 * H + j]; x1 = xr[1 * H + j];
            x2 = xr[2 * H + j]; x3 = xr[3 * H + j];
        }
        // broadcast h into smem
        for (int idx = tid; idx < Bc * (H / 4); idx += TPB) {
            int bb = idx / (H / 4), kk = idx % (H / 4);
            *(float4*)&hs[bb * Hp + kk * 4] = *(const float4*)&hbuf[bb * H + kk * 4];
        }
        __syncthreads();

        unsigned long long p0 = 0, p1 = 0, p2 = 0, p3 = 0;
        if (valid) {
#pragma unroll 4
            for (int k = kb; k < kb + KS; k += 4) {
                ulonglong2 hv = *(const ulonglong2*)&hrow[k];
                ulonglong2 q0 = *(const ulonglong2*)&w0[k];
                ulonglong2 q1 = *(const ulonglong2*)&w1[k];
                ulonglong2 q2 = *(const ulonglong2*)&w2[k];
                ulonglong2 q3 = *(const ulonglong2*)&w3[k];
                ffma2(p0, hv.x, q0.x); ffma2(p1, hv.x, q1.x);
                ffma2(p2, hv.x, q2.x); ffma2(p3, hv.x, q3.x);
                ffma2(p0, hv.y, q0.y); ffma2(p1, hv.y, q1.y);
                ffma2(p2, hv.y, q2.y); ffma2(p3, hv.y, q3.y);
            }
        }
        float a0 = f2sum(p0), a1 = f2sum(p1), a2 = f2sum(p2), a3 = f2sum(p3);
        part[tid * 4 + 0] = a0; part[tid * 4 + 1] = a1;
        part[tid * 4 + 2] = a2; part[tid * 4 + 3] = a3;
        __syncthreads();
        if (tid < TASKS && valid) {
#pragma unroll
            for (int s2 = 1; s2 < S; ++s2) {
                int o = (s2 * TASKS + tid) * 4;
                a0 += part[o + 0]; a1 += part[o + 1];
                a2 += part[o + 2]; a3 += part[o + 3];
            }
            float gi = a0 + x0, gf = a1 + x1, gg = a2 + x2, go = a3 + x3;
            float ig = 1.f / (1.f + expf(-gi));
            float fg = 1.f / (1.f + expf(-gf));
            float gv = tanhf(gg);
            float og = 1.f / (1.f + expf(-go));
            float c  = fg * cs[tt] + ig * gv;
            cs[tt] = c;
            float hn = og * tanhf(c);
            hbuf[b * H + j] = hn;
            if (WRITE_Y) yout[((size_t)b * Tc + t) * H + j] = hn;
        }
        grid_barrier(&s_phase);
    }

    if (!WRITE_Y) {
        for (int idx = tid; idx < Bc * U; idx += TPB) {
            int bb = idx / U, uu = idx % U;
            yout[bb * H + j0 + uu] = hbuf[bb * H + j0 + uu];
        }
    }
}

// -------------------- classifier head --------------------
__global__ void __launch_bounds__(256) head_kernel(
    const float* __restrict__ h0,
    const float* __restrict__ lw1, const float* __restrict__ lb1,
    const float* __restrict__ lw2, const float* __restrict__ lb2,
    float* __restrict__ outp)
{
    __shared__ float hv[512];
    __shared__ float hid[256];
    __shared__ float lg[2];
    int bidx = blockIdx.x, tid = threadIdx.x;
    hv[tid]       = h0[bidx * 512 + tid];
    hv[tid + 256] = h0[bidx * 512 + 256 + tid];
    __syncthreads();
    float acc = lb1[tid];
    const float* wr = &lw1[tid * 512];
#pragma unroll 4
    for (int k = 0; k < 512; k += 4) {
        float4 w = *(const float4*)&wr[k];
        acc += w.x * hv[k] + w.y * hv[k + 1] + w.z * hv[k + 2] + w.w * hv[k + 3];
    }
    hid[tid] = fmaxf(acc, 0.f);
    __syncthreads();
    if (tid < 64) {
        int c = tid >> 5, lane = tid & 31;
        float p = 0.f;
        for (int k = lane; k < 256; k += 32) p += hid[k] * lw2[c * 256 + k];
#pragma unroll
        for (int off = 16; off; off >>= 1) p += __shfl_down_sync(0xffffffffu, p, off);
        if (lane == 0) lg[c] = p + lb2[c];
    }
    __syncthreads();
    if (tid == 0) {
        float m = fmaxf(lg[0], lg[1]);
        float lse = m + logf(expf(lg[0] - m) + expf(lg[1] - m));
        outp[bidx * 2 + 0] = lg[0] - lse;
        outp[bidx * 2 + 1] = lg[1] - lse;
    }
}

// -------------------- launcher --------------------
static inline int lstm_smem_bytes(int H, int U) {
    int Hp = H + 4, R = 4 * U, TASKS = Bc * U;
    return 4 * (R * Hp + Bc * Hp + TASKS + 4 * TPB) + Bc * 4 + 16;
}

extern "C" void kernel_launch(void* const* d_in, const int* in_sizes, int n_in,
                              void* d_out, int out_size) {
    const float* x       = (const float*)d_in[0];
    const int*   lengths = (const int*)  d_in[1];
    const float* e1_wih  = (const float*)d_in[2];
    const float* e1_whh  = (const float*)d_in[3];
    const float* e1_b    = (const float*)d_in[4];
    const float* e2_wih  = (const float*)d_in[5];
    const float* e2_whh  = (const float*)d_in[6];
    const float* e2_b    = (const float*)d_in[7];
    const float* d1_wih  = (const float*)d_in[8];
    const float* d1_whh  = (const float*)d_in[9];
    const float* d1_b    = (const float*)d_in[10];
    const float* d2_wih  = (const float*)d_in[11];
    const float* d2_whh  = (const float*)d_in[12];
    const float* d2_b    = (const float*)d_in[13];
    const float* lw1     = (const float*)d_in[14];
    const float* lb1     = (const float*)d_in[15];
    const float* lw2     = (const float*)d_in[16];
    const float* lb2     = (const float*)d_in[17];
    float* out = (float*)d_out;

    float *xgp, *seqp, *hp, *h0p, *g0p;
    cudaGetSymbolAddress((void**)&xgp,  g_xg);
    cudaGetSymbolAddress((void**)&seqp, g_seq);
    cudaGetSymbolAddress((void**)&hp,   g_h);
    cudaGetSymbolAddress((void**)&h0p,  g_h0);
    cudaGetSymbolAddress((void**)&g0p,  g_g0);

    const int SMEM_E1 = lstm_smem_bytes(256, 2);
    const int SMEM_E2 = lstm_smem_bytes(512, 4);
    const int SMEM_D2 = lstm_smem_bytes(128, 1);
    cudaFuncSetAttribute((const void*)lstm_rec<256, 2, 4, true,  false>,
                         cudaFuncAttributeMaxDynamicSharedMemorySize, SMEM_E1);
    cudaFuncSetAttribute((const void*)lstm_rec<512, 4, 2, false, false>,
                         cudaFuncAttributeMaxDynamicSharedMemorySize, SMEM_E2);
    cudaFuncSetAttribute((const void*)lstm_rec<256, 2, 4, true,  true>,
                         cudaFuncAttributeMaxDynamicSharedMemorySize, SMEM_E1);
    cudaFuncSetAttribute((const void*)lstm_rec<128, 1, 8, true,  false>,
                         cudaFuncAttributeMaxDynamicSharedMemorySize, SMEM_D2);

    const int M = Bc * Tc;

    cudaMemsetAsync(d_out, 0, (size_t)out_size * sizeof(float));

    // encoder 1
    gemm_bias<<<dim3(1024 / 64, M / 64), 256>>>(x, e1_wih, e1_b, xgp, M, 1024, 128, lengths);
    lstm_rec<256, 2, 4, true, false><<<NCTA, TPB, SMEM_E1>>>(xgp, e1_whh, lengths, hp, seqp);

    // encoder 2
    gemm_bias<<<dim3(2048 / 64, M / 64), 256>>>(seqp, e2_wih, e2_b, xgp, M, 2048, 256, lengths);
    lstm_rec<512, 4, 2, false, false><<<NCTA, TPB, SMEM_E2>>>(xgp, e2_whh, lengths, hp, h0p);

    // decoder 1 (constant per-batch input)
    gemm_bias<<<dim3(1024 / 64, 1), 256>>>(h0p, d1_wih, d1_b, g0p, Bc, 1024, 512, nullptr);
    lstm_rec<256, 2, 4, true, true><<<NCTA, TPB, SMEM_E1>>>(g0p, d1_whh, lengths, hp, seqp);

    // decoder 2 -> d_out
    gemm_bias<<<dim3(512 / 64, M / 64), 256>>>(seqp, d2_wih, d2_b, xgp, M, 512, 256, lengths);
    lstm_rec<128, 1, 8, true, false><<<NCTA, TPB, SMEM_D2>>>(xgp, d2_whh, lengths, hp, out);

    // classifier head
    head_kernel<<<Bc, 256>>>(h0p, lw1, lb1, lw2, lb2, out + (size_t)out_size - 2 * Bc);
}